// round 15
// baseline (speedup 1.0000x reference)
#include <cuda_runtime.h>
#include <cstdint>

// Problem constants (fixed by the dataset)
#define B 8
#define N 2048
#define IN_F 512
#define OUT_F 128
#define RPW 2
#define TR 16

// Scratch (allocation-free rule: __device__ globals), 16B-aligned for float4
// wproj partials: 4 o-groups x 128 float4 columns (summed in k_xy, fixed order)
__device__ __align__(16) float4 g_wp1[4 * 128];
__device__ __align__(16) float4 g_wp2[4 * 128];
__device__ __align__(16) float g_x8[B * N];   // 0.125 * (emb1[b,i,:] . w1)
__device__ __align__(16) float g_y8[B * N];   // 0.125 * (emb1[b,i,:] . w2)

__device__ __forceinline__ float tanh_fast(float x) {
    float r;
    asm("tanh.approx.f32 %0, %1;" : "=f"(r) : "f"(x));
    return r;
}

__device__ __forceinline__ float4 f4add(float4 a, float4 b) {
    return make_float4(a.x + b.x, a.y + b.y, a.z + b.z, a.w + b.w);
}

// Order-preserving float->uint map (monotone: bigger float -> bigger uint)
__device__ __forceinline__ uint32_t f2ord(float f) {
    uint32_t x = __float_as_uint(f);
    return (x & 0x80000000u) ? ~x : (x | 0x80000000u);
}

// PDL primitives
__device__ __forceinline__ void pdl_wait() {
    asm volatile("griddepcontrol.wait;" ::: "memory");
}
__device__ __forceinline__ void pdl_trigger() {
    asm volatile("griddepcontrol.launch_dependents;" ::: "memory");
}

// K1: partial w-projections. Grid 32 = 8 f-groups x 4 o-groups.
//   g_wp[og][f4] = sum_{o in og} W4[o][f4] * a[o]
// Each thread: 2 x LDG.128 of W + smem a; block-level tree reduce over o.
__global__ void __launch_bounds__(256) k_wproj(const float* __restrict__ W,
                                               const float* __restrict__ a1,
                                               const float* __restrict__ a2) {
    const int tid = threadIdx.x;
    const int fg  = blockIdx.x & 7;              // f-group: 16 f4 columns
    const int og  = blockIdx.x >> 3;             // o-group: 32 o rows
    const int f4l = tid & 15;
    const int oc  = tid >> 4;                    // 0..15, 2 o each
    const int f4  = fg * 16 + f4l;

    __shared__ float sa1[32], sa2[32];
    __shared__ __align__(16) float4 red1[256], red2[256];
    if (tid < 32) {
        sa1[tid] = a1[og * 32 + tid];
        sa2[tid] = a2[og * 32 + tid];
    }
    __syncthreads();

    const float4* W4 = reinterpret_cast<const float4*>(W);   // [OUT_F][128]
    int o0 = og * 32 + oc * 2;
    float4 w0 = __ldg(&W4[(size_t)o0 * 128 + f4]);
    float4 w1 = __ldg(&W4[(size_t)(o0 + 1) * 128 + f4]);
    float A10 = sa1[oc * 2], A11 = sa1[oc * 2 + 1];
    float A20 = sa2[oc * 2], A21 = sa2[oc * 2 + 1];

    float4 acc1, acc2;
    acc1.x = fmaf(w0.x, A10, w1.x * A11);
    acc1.y = fmaf(w0.y, A10, w1.y * A11);
    acc1.z = fmaf(w0.z, A10, w1.z * A11);
    acc1.w = fmaf(w0.w, A10, w1.w * A11);
    acc2.x = fmaf(w0.x, A20, w1.x * A21);
    acc2.y = fmaf(w0.y, A20, w1.y * A21);
    acc2.z = fmaf(w0.z, A20, w1.z * A21);
    acc2.w = fmaf(w0.w, A20, w1.w * A21);

    red1[tid] = acc1;
    red2[tid] = acc2;
    __syncthreads();
    // tree-reduce over oc (high bits of tid)
#pragma unroll
    for (int s = 128; s >= 16; s >>= 1) {
        if (tid < s) {
            red1[tid] = f4add(red1[tid], red1[tid + s]);
            red2[tid] = f4add(red2[tid], red2[tid + s]);
        }
        __syncthreads();
    }
    if (tid < 16) {
        g_wp1[og * 128 + fg * 16 + tid] = red1[tid];
        g_wp2[og * 128 + fg * 16 + tid] = red2[tid];
    }
    pdl_trigger();
}

// K2: per-warp dual dot products, 2 rows per warp. PDL prologue: row 0's emb
// loads (independent of wproj) issued before the wait. w1/w2 assembled from
// the 4 o-group partials in fixed order (deterministic).
__global__ void __launch_bounds__(256) k_xy(const float* __restrict__ emb) {
    int warp = (blockIdx.x * blockDim.x + threadIdx.x) >> 5;
    int lane = threadIdx.x & 31;
    int row0 = warp * RPW;                     // 8192 warps cover 16384 rows

    const float4* rowp0 = reinterpret_cast<const float4*>(emb + (size_t)row0 * IN_F);
    float4 e0[4];
#pragma unroll
    for (int k = 0; k < 4; k++) e0[k] = rowp0[lane + 32 * k];

    pdl_wait();   // wproj partials now visible

    float4 W1[4], W2[4];
#pragma unroll
    for (int k = 0; k < 4; k++) {
        int idx = lane + 32 * k;
        W1[k] = f4add(f4add(g_wp1[idx], g_wp1[128 + idx]),
                      f4add(g_wp1[256 + idx], g_wp1[384 + idx]));
        W2[k] = f4add(f4add(g_wp2[idx], g_wp2[128 + idx]),
                      f4add(g_wp2[256 + idx], g_wp2[384 + idx]));
    }

    float s1[RPW] = {0.f, 0.f}, s2[RPW] = {0.f, 0.f};
#pragma unroll
    for (int k = 0; k < 4; k++) {
        s1[0] = fmaf(e0[k].x, W1[k].x, fmaf(e0[k].y, W1[k].y, fmaf(e0[k].z, W1[k].z, fmaf(e0[k].w, W1[k].w, s1[0]))));
        s2[0] = fmaf(e0[k].x, W2[k].x, fmaf(e0[k].y, W2[k].y, fmaf(e0[k].z, W2[k].z, fmaf(e0[k].w, W2[k].w, s2[0]))));
    }
    {
        const float4* rowp1 = reinterpret_cast<const float4*>(emb + (size_t)(row0 + 1) * IN_F);
#pragma unroll
        for (int k = 0; k < 4; k++) {
            float4 e = rowp1[lane + 32 * k];
            s1[1] = fmaf(e.x, W1[k].x, fmaf(e.y, W1[k].y, fmaf(e.z, W1[k].z, fmaf(e.w, W1[k].w, s1[1]))));
            s2[1] = fmaf(e.x, W2[k].x, fmaf(e.y, W2[k].y, fmaf(e.z, W2[k].z, fmaf(e.w, W2[k].w, s2[1]))));
        }
    }
#pragma unroll
    for (int off = 16; off; off >>= 1) {
#pragma unroll
        for (int r = 0; r < RPW; r++) {
            s1[r] += __shfl_down_sync(0xffffffffu, s1[r], off);
            s2[r] += __shfl_down_sync(0xffffffffu, s2[r], off);
        }
    }
    if (lane == 0) {
#pragma unroll
        for (int r = 0; r < RPW; r++) {
            g_x8[row0 + r] = s1[r] * 0.125f;
            g_y8[row0 + r] = s2[r] * 0.125f;
        }
    }
    pdl_trigger();
}

// K3: fused select + output (byte-identical to the passing R14 kernel).
__global__ void __launch_bounds__(256) k_out(const int* __restrict__ n_src,
                                             const int* __restrict__ ns_tgt,
                                             float* __restrict__ out) {
    const int b    = blockIdx.x >> 7;      // 128 tiles per batch
    const int tile = blockIdx.x & 127;
    const int row0 = b * N + tile * TR;
    const int tid  = threadIdx.x;
    const int t0 = tid, t1 = tid + 256;

    // ── PDL prologue: harness inputs, independent of k_xy ────────────────
    const int ns   = ns_tgt[b];
    const int nsrc = n_src[b];
    const int kb   = (int)((float)nsrc * 0.4f);   // fp32 mul + trunc = ref
    const float sc = 1.0f / ((float)nsrc * 0.4f);

    pdl_wait();   // x8/y8 now visible

    const float4* y4 = reinterpret_cast<const float4*>(g_y8 + b * N);
    const float4* x4 = reinterpret_cast<const float4*>(g_x8 + b * N);
    float4 yA = y4[t0], yB = y4[t1];
    float4 xA = x4[t0], xB = x4[t1];

    // ordered keys + column indices for this thread's 8 columns
    uint32_t u[8];
    u[0] = f2ord(yA.x); u[1] = f2ord(yA.y); u[2] = f2ord(yA.z); u[3] = f2ord(yA.w);
    u[4] = f2ord(yB.x); u[5] = f2ord(yB.y); u[6] = f2ord(yB.z); u[7] = f2ord(yB.w);
    int jc[8];
#pragma unroll
    for (int e = 0; e < 4; e++) { jc[e] = 4 * tid + e; jc[4 + e] = 4 * tid + 1024 + e; }
    bool vj[8];
#pragma unroll
    for (int e = 0; e < 8; e++) vj[e] = (jc[e] < ns);

    // ── 3-pass radix select of the kb-th largest key among valid columns ─
    __shared__ uint32_t bins[2048];
    __shared__ uint32_t spart[256];
    __shared__ uint32_t s_uhi, s_tgt;
    __shared__ int s_cnt, s_minj;

    uint32_t uhi = 0, target = (uint32_t)kb;
    const int      shifts[3]  = {21, 10, 0};
    const uint32_t fmask[3]   = {0x7FFu, 0x7FFu, 0x3FFu};
    const uint32_t himask[3]  = {0u, 0xFFE00000u, 0xFFFFFC00u};

#pragma unroll
    for (int p = 0; p < 3; p++) {
        for (int i = tid; i < 2048; i += 256) bins[i] = 0;
        __syncthreads();
#pragma unroll
        for (int e = 0; e < 8; e++) {
            if (vj[e] && ((u[e] & himask[p]) == uhi))
                atomicAdd(&bins[(u[e] >> shifts[p]) & fmask[p]], 1u);
        }
        __syncthreads();
        // chunk suffix totals (thread c owns bins[c*8 .. c*8+8))
        uint32_t csum = 0;
#pragma unroll
        for (int i = 7; i >= 0; i--) csum += bins[tid * 8 + i];
        spart[tid] = csum;
        __syncthreads();
        for (int off = 1; off < 256; off <<= 1) {
            uint32_t v = (tid + off < 256) ? spart[tid + off] : 0u;
            __syncthreads();
            spart[tid] += v;
            __syncthreads();
        }
        // locate target bin (exactly one thread matches)
        if (spart[tid] >= target && (tid == 255 || spart[tid + 1] < target)) {
            uint32_t acc = (tid == 255) ? 0u : spart[tid + 1];
#pragma unroll
            for (int i = 7; i >= 0; i--) {
                uint32_t bc = bins[tid * 8 + i];
                if (acc + bc >= target) {
                    s_uhi = uhi | ((uint32_t)(tid * 8 + i) << shifts[p]);
                    s_tgt = target - acc;   // rank within this bin (1-based)
                    break;
                }
                acc += bc;
            }
        }
        __syncthreads();
        uhi = s_uhi;
        target = s_tgt;
        __syncthreads();
    }
    const uint32_t ustar = uhi;
    const int rprime = (int)target;   // 1-based rank within equal-ustar group

    // ── j*: rprime-th smallest index among valid columns with u == ustar ─
    if (tid == 0) { s_cnt = 0; s_minj = 0x7FFFFFFF; }
    __syncthreads();
    {
        int lc = 0, lmin = 0x7FFFFFFF;
#pragma unroll
        for (int e = 0; e < 8; e++)
            if (vj[e] && u[e] == ustar) { lc++; lmin = min(lmin, jc[e]); }
        if (lc) { atomicAdd(&s_cnt, lc); atomicMin(&s_minj, lmin); }
    }
    __syncthreads();
    int jstar;
    const int cntEq = s_cnt;
    if (rprime == 1)            jstar = s_minj;
    else if (rprime >= cntEq)   jstar = N - 1;     // include all equals
    else {
        // rare tie path: binary search smallest m with count(j<=m, u==ustar) >= rprime
        int lo = 0, hi = N - 1;
        while (lo < hi) {
            int mid = (lo + hi) >> 1;
            if (tid == 0) s_cnt = 0;
            __syncthreads();
            int c = 0;
#pragma unroll
            for (int e = 0; e < 8; e++)
                c += (vj[e] && u[e] == ustar && jc[e] <= mid);
            if (c) atomicAdd(&s_cnt, c);
            __syncthreads();
            if (s_cnt >= rprime) hi = mid; else lo = mid + 1;
            __syncthreads();
        }
        jstar = lo;
    }

    // ── build sentinels: columns in registers, rows in smem ──────────────
    const float NEG = -1e30f;
    float4 xmA, xmB;
    {
#define COLACT(e) (vj[e] && (jc[e] < nsrc) && (u[e] > ustar || (u[e] == ustar && jc[e] <= jstar)))
        xmA.x = COLACT(0) ? xA.x : NEG;
        xmA.y = COLACT(1) ? xA.y : NEG;
        xmA.z = COLACT(2) ? xA.z : NEG;
        xmA.w = COLACT(3) ? xA.w : NEG;
        xmB.x = COLACT(4) ? xB.x : NEG;
        xmB.y = COLACT(5) ? xB.y : NEG;
        xmB.z = COLACT(6) ? xB.z : NEG;
        xmB.w = COLACT(7) ? xB.w : NEG;
#undef COLACT
    }
    __shared__ float s_x[TR], s_ym[TR];
    if (tid < TR) {
        int irow = tile * TR + tid;                 // index within batch
        float yi = g_y8[row0 + tid];
        float xi = g_x8[row0 + tid];
        uint32_t ui = f2ord(yi);
        bool act = (irow < ns) && (irow < nsrc) &&
                   (ui > ustar || (ui == ustar && irow <= jstar));
        s_x[tid]  = xi;
        s_ym[tid] = act ? yi : NEG;
    }
    __syncthreads();

    // ── proven store loop ─────────────────────────────────────────────────
#pragma unroll 4
    for (int r = 0; r < TR; r++) {
        float xi  = s_x[r];
        float ymi = s_ym[r];
        float4* o4 = reinterpret_cast<float4*>(out + (size_t)(row0 + r) * N);

        float4 rA, rB;
        {
            float e0 = xi + yA.x, e1 = xi + yA.y, e2 = xi + yA.z, e3 = xi + yA.w;
            rA.x = (fminf(e0, xmA.x + ymi) > 0.f) ? sc * tanh_fast(e0) : 0.f;
            rA.y = (fminf(e1, xmA.y + ymi) > 0.f) ? sc * tanh_fast(e1) : 0.f;
            rA.z = (fminf(e2, xmA.z + ymi) > 0.f) ? sc * tanh_fast(e2) : 0.f;
            rA.w = (fminf(e3, xmA.w + ymi) > 0.f) ? sc * tanh_fast(e3) : 0.f;
        }
        {
            float e0 = xi + yB.x, e1 = xi + yB.y, e2 = xi + yB.z, e3 = xi + yB.w;
            rB.x = (fminf(e0, xmB.x + ymi) > 0.f) ? sc * tanh_fast(e0) : 0.f;
            rB.y = (fminf(e1, xmB.y + ymi) > 0.f) ? sc * tanh_fast(e1) : 0.f;
            rB.z = (fminf(e2, xmB.z + ymi) > 0.f) ? sc * tanh_fast(e2) : 0.f;
            rB.w = (fminf(e3, xmB.w + ymi) > 0.f) ? sc * tanh_fast(e3) : 0.f;
        }
        __stcs(&o4[t0], rA);   // streaming store: output >> L2, evict-first
        __stcs(&o4[t1], rB);
    }
}

// Helper: launch with programmatic stream serialization (PDL)
template <typename... Args>
static void launch_pdl(void (*kernel)(Args...), dim3 grid, dim3 block,
                       cudaStream_t stream, Args... args) {
    cudaLaunchConfig_t cfg = {};
    cfg.gridDim = grid;
    cfg.blockDim = block;
    cfg.dynamicSmemBytes = 0;
    cfg.stream = stream;
    cudaLaunchAttribute attr[1];
    attr[0].id = cudaLaunchAttributeProgrammaticStreamSerialization;
    attr[0].val.programmaticStreamSerializationAllowed = 1;
    cfg.attrs = attr;
    cfg.numAttrs = 1;
    cudaLaunchKernelEx(&cfg, kernel, args...);
}

extern "C" void kernel_launch(void* const* d_in, const int* in_sizes, int n_in,
                              void* d_out, int out_size) {
    const float* emb1  = (const float*)d_in[0];
    const float* W     = (const float*)d_in[1];
    const float* a1    = (const float*)d_in[2];
    const float* a2    = (const float*)d_in[3];
    const int*   n_src = (const int*)d_in[4];
    const int*   nstgt = (const int*)d_in[5];
    float* out = (float*)d_out;
    cudaStream_t s = 0;  // capture stream (legacy default under graph capture)

    k_wproj<<<32, 256, 0, s>>>(W, a1, a2);
    launch_pdl(k_xy, dim3((B * N / RPW) / 8), dim3(256), s, emb1);
    launch_pdl(k_out, dim3(B * (N / TR)), dim3(256), s, n_src, nstgt, out);
}

// round 17
// speedup vs baseline: 1.1436x; 1.1436x over previous
#include <cuda_runtime.h>
#include <cstdint>

// Problem constants (fixed by the dataset)
#define B 8
#define N 2048
#define IN_F 512
#define OUT_F 128
#define RPW 2
#define TR 16

// Scratch (allocation-free rule: __device__ globals), 16B-aligned for float4
__device__ __align__(16) float g_w1[IN_F];
__device__ __align__(16) float g_w2[IN_F];
__device__ __align__(16) float g_x8[B * N];   // 0.125 * (emb1[b,i,:] . w1)
__device__ __align__(16) float g_y8[B * N];   // 0.125 * (emb1[b,i,:] . w2)

__device__ __forceinline__ float tanh_fast(float x) {
    float r;
    asm("tanh.approx.f32 %0, %1;" : "=f"(r) : "f"(x));
    return r;
}

__device__ __forceinline__ float4 f4add(float4 a, float4 b) {
    return make_float4(a.x + b.x, a.y + b.y, a.z + b.z, a.w + b.w);
}

// Order-preserving float->uint map (monotone: bigger float -> bigger uint)
__device__ __forceinline__ uint32_t f2ord(float f) {
    uint32_t x = __float_as_uint(f);
    return (x & 0x80000000u) ? ~x : (x | 0x80000000u);
}

// PDL primitives
__device__ __forceinline__ void pdl_wait() {
    asm volatile("griddepcontrol.wait;" ::: "memory");
}
__device__ __forceinline__ void pdl_trigger() {
    asm volatile("griddepcontrol.launch_dependents;" ::: "memory");
}

// K1: w1 = W^T a1, w2 = W^T a2 — FINAL values. Grid 8 (f-split only):
// block fg owns 16 float4 columns (8 x 16 = 128 = IN_F/4 — bounds ok).
// Thread (f4l, oc): 8 x LDG.128 of W, smem-staged a; deterministic smem
// tree reduce over the 16 oc groups.
__global__ void __launch_bounds__(256) k_wproj(const float* __restrict__ W,
                                               const float* __restrict__ a1,
                                               const float* __restrict__ a2) {
    const int tid = threadIdx.x;
    const int fg  = blockIdx.x;                  // 0..7
    const int f4l = tid & 15;
    const int oc  = tid >> 4;                    // 0..15, 8 o each
    const int f4  = fg * 16 + f4l;               // 0..127 (in bounds)

    __shared__ float sa1[OUT_F], sa2[OUT_F];
    __shared__ __align__(16) float4 red1[256], red2[256];
    if (tid < OUT_F) {
        sa1[tid] = a1[tid];
        sa2[tid] = a2[tid];
    }
    __syncthreads();

    const float4* W4 = reinterpret_cast<const float4*>(W);   // [OUT_F][128]
    float4 acc1 = {0.f, 0.f, 0.f, 0.f};
    float4 acc2 = {0.f, 0.f, 0.f, 0.f};
#pragma unroll
    for (int i = 0; i < 8; i++) {
        int o = oc * 8 + i;
        float4 w = __ldg(&W4[(size_t)o * 128 + f4]);
        float A1 = sa1[o], A2 = sa2[o];
        acc1.x = fmaf(w.x, A1, acc1.x); acc1.y = fmaf(w.y, A1, acc1.y);
        acc1.z = fmaf(w.z, A1, acc1.z); acc1.w = fmaf(w.w, A1, acc1.w);
        acc2.x = fmaf(w.x, A2, acc2.x); acc2.y = fmaf(w.y, A2, acc2.y);
        acc2.z = fmaf(w.z, A2, acc2.z); acc2.w = fmaf(w.w, A2, acc2.w);
    }
    red1[tid] = acc1;
    red2[tid] = acc2;
    __syncthreads();
#pragma unroll
    for (int s = 128; s >= 16; s >>= 1) {
        if (tid < s) {
            red1[tid] = f4add(red1[tid], red1[tid + s]);
            red2[tid] = f4add(red2[tid], red2[tid + s]);
        }
        __syncthreads();
    }
    if (tid < 16) {
        reinterpret_cast<float4*>(g_w1)[fg * 16 + tid] = red1[tid];
        reinterpret_cast<float4*>(g_w2)[fg * 16 + tid] = red2[tid];
    }
    pdl_trigger();
}

// K2: per-warp dual dot products, 2 rows per warp. PDL prologue: row 0's emb
// loads (independent of wproj) issued before the wait. (Byte-identical to
// the 43.2us R14 version.)
__global__ void __launch_bounds__(256) k_xy(const float* __restrict__ emb) {
    int warp = (blockIdx.x * blockDim.x + threadIdx.x) >> 5;
    int lane = threadIdx.x & 31;
    int row0 = warp * RPW;                     // 8192 warps cover 16384 rows

    const float4* rowp0 = reinterpret_cast<const float4*>(emb + (size_t)row0 * IN_F);
    float4 e0[4];
#pragma unroll
    for (int k = 0; k < 4; k++) e0[k] = rowp0[lane + 32 * k];

    pdl_wait();   // w1/w2 now visible

    const float4* w1 = reinterpret_cast<const float4*>(g_w1);
    const float4* w2 = reinterpret_cast<const float4*>(g_w2);
    float4 W1[4], W2[4];
#pragma unroll
    for (int k = 0; k < 4; k++) {
        W1[k] = w1[lane + 32 * k];
        W2[k] = w2[lane + 32 * k];
    }

    float s1[RPW] = {0.f, 0.f}, s2[RPW] = {0.f, 0.f};
#pragma unroll
    for (int k = 0; k < 4; k++) {
        s1[0] = fmaf(e0[k].x, W1[k].x, fmaf(e0[k].y, W1[k].y, fmaf(e0[k].z, W1[k].z, fmaf(e0[k].w, W1[k].w, s1[0]))));
        s2[0] = fmaf(e0[k].x, W2[k].x, fmaf(e0[k].y, W2[k].y, fmaf(e0[k].z, W2[k].z, fmaf(e0[k].w, W2[k].w, s2[0]))));
    }
    {
        const float4* rowp1 = reinterpret_cast<const float4*>(emb + (size_t)(row0 + 1) * IN_F);
#pragma unroll
        for (int k = 0; k < 4; k++) {
            float4 e = rowp1[lane + 32 * k];
            s1[1] = fmaf(e.x, W1[k].x, fmaf(e.y, W1[k].y, fmaf(e.z, W1[k].z, fmaf(e.w, W1[k].w, s1[1]))));
            s2[1] = fmaf(e.x, W2[k].x, fmaf(e.y, W2[k].y, fmaf(e.z, W2[k].z, fmaf(e.w, W2[k].w, s2[1]))));
        }
    }
#pragma unroll
    for (int off = 16; off; off >>= 1) {
#pragma unroll
        for (int r = 0; r < RPW; r++) {
            s1[r] += __shfl_down_sync(0xffffffffu, s1[r], off);
            s2[r] += __shfl_down_sync(0xffffffffu, s2[r], off);
        }
    }
    if (lane == 0) {
#pragma unroll
        for (int r = 0; r < RPW; r++) {
            g_x8[row0 + r] = s1[r] * 0.125f;
            g_y8[row0 + r] = s2[r] * 0.125f;
        }
    }
    pdl_trigger();
}

// K3: fused select + output (R14 logic; shuffle suffix-scan in the radix
// select — verified semantically identical to the proven Hillis-Steele scan).
__global__ void __launch_bounds__(256) k_out(const int* __restrict__ n_src,
                                             const int* __restrict__ ns_tgt,
                                             float* __restrict__ out) {
    const int b    = blockIdx.x >> 7;      // 128 tiles per batch
    const int tile = blockIdx.x & 127;
    const int row0 = b * N + tile * TR;
    const int tid  = threadIdx.x;
    const int lane = tid & 31;
    const int wid  = tid >> 5;             // 0..7
    const int t0 = tid, t1 = tid + 256;

    // ── PDL prologue: harness inputs, independent of k_xy ────────────────
    const int ns   = ns_tgt[b];
    const int nsrc = n_src[b];
    const int kb   = (int)((float)nsrc * 0.4f);   // fp32 mul + trunc = ref
    const float sc = 1.0f / ((float)nsrc * 0.4f);

    pdl_wait();   // x8/y8 now visible

    const float4* y4 = reinterpret_cast<const float4*>(g_y8 + b * N);
    const float4* x4 = reinterpret_cast<const float4*>(g_x8 + b * N);
    float4 yA = y4[t0], yB = y4[t1];
    float4 xA = x4[t0], xB = x4[t1];

    // ordered keys + column indices for this thread's 8 columns
    uint32_t u[8];
    u[0] = f2ord(yA.x); u[1] = f2ord(yA.y); u[2] = f2ord(yA.z); u[3] = f2ord(yA.w);
    u[4] = f2ord(yB.x); u[5] = f2ord(yB.y); u[6] = f2ord(yB.z); u[7] = f2ord(yB.w);
    int jc[8];
#pragma unroll
    for (int e = 0; e < 4; e++) { jc[e] = 4 * tid + e; jc[4 + e] = 4 * tid + 1024 + e; }
    bool vj[8];
#pragma unroll
    for (int e = 0; e < 8; e++) vj[e] = (jc[e] < ns);

    // ── 3-pass radix select of the kb-th largest key among valid columns ─
    __shared__ uint32_t bins[2048];
    __shared__ uint32_t wtot[8];
    __shared__ uint32_t s_uhi, s_tgt;
    __shared__ int s_cnt, s_minj;

    uint32_t uhi = 0, target = (uint32_t)kb;
    const int      shifts[3]  = {21, 10, 0};
    const uint32_t fmask[3]   = {0x7FFu, 0x7FFu, 0x3FFu};
    const uint32_t himask[3]  = {0u, 0xFFE00000u, 0xFFFFFC00u};

#pragma unroll
    for (int p = 0; p < 3; p++) {
        for (int i = tid; i < 2048; i += 256) bins[i] = 0;
        __syncthreads();
#pragma unroll
        for (int e = 0; e < 8; e++) {
            if (vj[e] && ((u[e] & himask[p]) == uhi))
                atomicAdd(&bins[(u[e] >> shifts[p]) & fmask[p]], 1u);
        }
        __syncthreads();
        // chunk totals: thread owns bins[tid*8 .. tid*8+8)
        uint32_t csum = 0;
#pragma unroll
        for (int i = 7; i >= 0; i--) csum += bins[tid * 8 + i];
        // warp suffix-scan (inclusive): v = sum over lanes >= lane, this warp
        uint32_t v = csum;
#pragma unroll
        for (int off = 1; off < 32; off <<= 1) {
            uint32_t o = __shfl_down_sync(0xffffffffu, v, off);
            if (lane + off < 32) v += o;
        }
        if (lane == 0) wtot[wid] = v;     // warp total = suffix at lane 0
        __syncthreads();
        uint32_t add = 0;
#pragma unroll
        for (int w = 0; w < 8; w++) add += (w > wid) ? wtot[w] : 0u;
        uint32_t ssum = v + add;          // inclusive suffix over all 256 chunks
        uint32_t snext = ssum - csum;     // suffix excluding own chunk
        // locate target bin (exactly one thread matches)
        if (ssum >= target && snext < target) {
            uint32_t acc = snext;
#pragma unroll
            for (int i = 7; i >= 0; i--) {
                uint32_t bc = bins[tid * 8 + i];
                if (acc + bc >= target) {
                    s_uhi = uhi | ((uint32_t)(tid * 8 + i) << shifts[p]);
                    s_tgt = target - acc;   // rank within this bin (1-based)
                    break;
                }
                acc += bc;
            }
        }
        __syncthreads();
        uhi = s_uhi;
        target = s_tgt;
        __syncthreads();
    }
    const uint32_t ustar = uhi;
    const int rprime = (int)target;   // 1-based rank within equal-ustar group

    // ── j*: rprime-th smallest index among valid columns with u == ustar ─
    if (tid == 0) { s_cnt = 0; s_minj = 0x7FFFFFFF; }
    __syncthreads();
    {
        int lc = 0, lmin = 0x7FFFFFFF;
#pragma unroll
        for (int e = 0; e < 8; e++)
            if (vj[e] && u[e] == ustar) { lc++; lmin = min(lmin, jc[e]); }
        if (lc) { atomicAdd(&s_cnt, lc); atomicMin(&s_minj, lmin); }
    }
    __syncthreads();
    int jstar;
    const int cntEq = s_cnt;
    if (rprime == 1)            jstar = s_minj;
    else if (rprime >= cntEq)   jstar = N - 1;     // include all equals
    else {
        // rare tie path: binary search smallest m with count(j<=m, u==ustar) >= rprime
        int lo = 0, hi = N - 1;
        while (lo < hi) {
            int mid = (lo + hi) >> 1;
            if (tid == 0) s_cnt = 0;
            __syncthreads();
            int c = 0;
#pragma unroll
            for (int e = 0; e < 8; e++)
                c += (vj[e] && u[e] == ustar && jc[e] <= mid);
            if (c) atomicAdd(&s_cnt, c);
            __syncthreads();
            if (s_cnt >= rprime) hi = mid; else lo = mid + 1;
            __syncthreads();
        }
        jstar = lo;
    }

    // ── build sentinels: columns in registers, rows in smem ──────────────
    const float NEG = -1e30f;
    float4 xmA, xmB;
    {
#define COLACT(e) (vj[e] && (jc[e] < nsrc) && (u[e] > ustar || (u[e] == ustar && jc[e] <= jstar)))
        xmA.x = COLACT(0) ? xA.x : NEG;
        xmA.y = COLACT(1) ? xA.y : NEG;
        xmA.z = COLACT(2) ? xA.z : NEG;
        xmA.w = COLACT(3) ? xA.w : NEG;
        xmB.x = COLACT(4) ? xB.x : NEG;
        xmB.y = COLACT(5) ? xB.y : NEG;
        xmB.z = COLACT(6) ? xB.z : NEG;
        xmB.w = COLACT(7) ? xB.w : NEG;
#undef COLACT
    }
    __shared__ float s_x[TR], s_ym[TR];
    if (tid < TR) {
        int irow = tile * TR + tid;                 // index within batch
        float yi = g_y8[row0 + tid];
        float xi = g_x8[row0 + tid];
        uint32_t ui = f2ord(yi);
        bool act = (irow < ns) && (irow < nsrc) &&
                   (ui > ustar || (ui == ustar && irow <= jstar));
        s_x[tid]  = xi;
        s_ym[tid] = act ? yi : NEG;
    }
    __syncthreads();

    // ── proven store loop ─────────────────────────────────────────────────
#pragma unroll 4
    for (int r = 0; r < TR; r++) {
        float xi  = s_x[r];
        float ymi = s_ym[r];
        float4* o4 = reinterpret_cast<float4*>(out + (size_t)(row0 + r) * N);

        float4 rA, rB;
        {
            float e0 = xi + yA.x, e1 = xi + yA.y, e2 = xi + yA.z, e3 = xi + yA.w;
            rA.x = (fminf(e0, xmA.x + ymi) > 0.f) ? sc * tanh_fast(e0) : 0.f;
            rA.y = (fminf(e1, xmA.y + ymi) > 0.f) ? sc * tanh_fast(e1) : 0.f;
            rA.z = (fminf(e2, xmA.z + ymi) > 0.f) ? sc * tanh_fast(e2) : 0.f;
            rA.w = (fminf(e3, xmA.w + ymi) > 0.f) ? sc * tanh_fast(e3) : 0.f;
        }
        {
            float e0 = xi + yB.x, e1 = xi + yB.y, e2 = xi + yB.z, e3 = xi + yB.w;
            rB.x = (fminf(e0, xmB.x + ymi) > 0.f) ? sc * tanh_fast(e0) : 0.f;
            rB.y = (fminf(e1, xmB.y + ymi) > 0.f) ? sc * tanh_fast(e1) : 0.f;
            rB.z = (fminf(e2, xmB.z + ymi) > 0.f) ? sc * tanh_fast(e2) : 0.f;
            rB.w = (fminf(e3, xmB.w + ymi) > 0.f) ? sc * tanh_fast(e3) : 0.f;
        }
        __stcs(&o4[t0], rA);   // streaming store: output >> L2, evict-first
        __stcs(&o4[t1], rB);
    }
}

// Helper: launch with programmatic stream serialization (PDL)
template <typename... Args>
static void launch_pdl(void (*kernel)(Args...), dim3 grid, dim3 block,
                       cudaStream_t stream, Args... args) {
    cudaLaunchConfig_t cfg = {};
    cfg.gridDim = grid;
    cfg.blockDim = block;
    cfg.dynamicSmemBytes = 0;
    cfg.stream = stream;
    cudaLaunchAttribute attr[1];
    attr[0].id = cudaLaunchAttributeProgrammaticStreamSerialization;
    attr[0].val.programmaticStreamSerializationAllowed = 1;
    cfg.attrs = attr;
    cfg.numAttrs = 1;
    cudaLaunchKernelEx(&cfg, kernel, args...);
}

extern "C" void kernel_launch(void* const* d_in, const int* in_sizes, int n_in,
                              void* d_out, int out_size) {
    const float* emb1  = (const float*)d_in[0];
    const float* W     = (const float*)d_in[1];
    const float* a1    = (const float*)d_in[2];
    const float* a2    = (const float*)d_in[3];
    const int*   n_src = (const int*)d_in[4];
    const int*   nstgt = (const int*)d_in[5];
    float* out = (float*)d_out;
    cudaStream_t s = 0;  // capture stream (legacy default under graph capture)

    k_wproj<<<8, 256, 0, s>>>(W, a1, a2);
    launch_pdl(k_xy, dim3((B * N / RPW) / 8), dim3(256), s, emb1);
    launch_pdl(k_out, dim3(B * (N / TR)), dim3(256), s, n_src, nstgt, out);
}